// round 17
// baseline (speedup 1.0000x reference)
#include <cuda_runtime.h>

// BiologicalNormalization: 3 chained per-row LayerNorms (D=512), gathered
// per-sample affine params; trailing sigmoid-gated blend is the identity.
//
// R17: R16 + rolling param prefetch across ALL passes. The 16 prefetch
// registers (pgg/pbb, first 2 float4 pairs of each pass's gamma/beta) are
// consumed in normalize i=0,1 of pass p and immediately re-issued as the
// prefetch for pass p+1 -> each pass's post-reduction param fetch is fully
// covered by the previous pass's tail + current stats/reduction phase.

#define B_DIM 2048
#define S_DIM 128
#define D_DIM 512
#define THREADS 128
#define WARPS 4
#define ROWS 2            // rows per warp -> 8 rows per block
#define SPLIT 16          // blocks per sample

__global__ __launch_bounds__(THREADS, 7)
void bionorm_kernel(const float* __restrict__ x,
                    const int* __restrict__ pathway_ids,
                    const int* __restrict__ compartment_ids,
                    const int* __restrict__ cell_type_ids,
                    const float* __restrict__ pg, const float* __restrict__ pb,
                    const float* __restrict__ cg, const float* __restrict__ cb,
                    const float* __restrict__ tg, const float* __restrict__ tb,
                    float* __restrict__ out)
{
    const int blk = blockIdx.x;
    const int b = blk >> 4;           // sample
    const int lane = threadIdx.x & 31;

    const int p_id = __ldg(pathway_ids + b);
    const int c_id = __ldg(compartment_ids + b);
    const int t_id = __ldg(cell_type_ids + b);

    const size_t elem0 = ((size_t)b * S_DIM
                        + ((blk & 15) * (WARPS * ROWS) + (threadIdx.x >> 5) * ROWS))
                        * D_DIM;
    const float4* __restrict__ xr = reinterpret_cast<const float4*>(x + elem0);

    // Front-batched load of 2 full rows: 8 independent LDG.128.
    float4 v[ROWS][4];
    #pragma unroll
    for (int r = 0; r < ROWS; r++)
        #pragma unroll
        for (int i = 0; i < 4; i++)
            v[r][i] = xr[r * (D_DIM / 4) + lane + 32 * i];

    const float4* __restrict__ gtab[3] = {
        reinterpret_cast<const float4*>(pg + (size_t)p_id * D_DIM),
        reinterpret_cast<const float4*>(cg + (size_t)c_id * D_DIM),
        reinterpret_cast<const float4*>(tg + (size_t)t_id * D_DIM)
    };
    const float4* __restrict__ btab[3] = {
        reinterpret_cast<const float4*>(pb + (size_t)p_id * D_DIM),
        reinterpret_cast<const float4*>(cb + (size_t)c_id * D_DIM),
        reinterpret_cast<const float4*>(tb + (size_t)t_id * D_DIM)
    };

    // Prefetch pass-0's first two param pairs alongside the x loads.
    float4 pgg[2], pbb[2];
    #pragma unroll
    for (int i = 0; i < 2; i++) {
        pgg[i] = __ldg(gtab[0] + lane + 32 * i);
        pbb[i] = __ldg(btab[0] + lane + 32 * i);
    }

    const float inv_d = 1.0f / (float)D_DIM;
    const float eps = 1e-5f;

    #pragma unroll
    for (int p = 0; p < 3; p++) {
        const float4* __restrict__ gvp = gtab[p];
        const float4* __restrict__ bvp = btab[p];

        float sum[ROWS], sq[ROWS];
        #pragma unroll
        for (int r = 0; r < ROWS; r++) {
            float s = 0.f, q = 0.f;
            #pragma unroll
            for (int i = 0; i < 4; i++) {
                s += v[r][i].x + v[r][i].y + v[r][i].z + v[r][i].w;
                q = fmaf(v[r][i].x, v[r][i].x, q);
                q = fmaf(v[r][i].y, v[r][i].y, q);
                q = fmaf(v[r][i].z, v[r][i].z, q);
                q = fmaf(v[r][i].w, v[r][i].w, q);
            }
            sum[r] = s; sq[r] = q;
        }
        #pragma unroll
        for (int o = 16; o > 0; o >>= 1) {
            #pragma unroll
            for (int r = 0; r < ROWS; r++) {
                sum[r] += __shfl_xor_sync(0xffffffffu, sum[r], o);
                sq[r]  += __shfl_xor_sync(0xffffffffu, sq[r],  o);
            }
        }

        // a = rstd, c = -mean*rstd  ->  normalized = fma(v, a, c)
        float a[ROWS], c[ROWS];
        #pragma unroll
        for (int r = 0; r < ROWS; r++) {
            const float mean = sum[r] * inv_d;
            const float var = fmaf(-mean, mean, sq[r] * inv_d);
            a[r] = rsqrtf(var + eps);
            c[r] = -mean * a[r];
        }

        // Normalize i=0,1 from the prefetched registers.
        #pragma unroll
        for (int i = 0; i < 2; i++) {
            const float4 gg = pgg[i];
            const float4 bb = pbb[i];
            #pragma unroll
            for (int r = 0; r < ROWS; r++) {
                v[r][i].x = fmaf(fmaf(v[r][i].x, a[r], c[r]), gg.x, bb.x);
                v[r][i].y = fmaf(fmaf(v[r][i].y, a[r], c[r]), gg.y, bb.y);
                v[r][i].z = fmaf(fmaf(v[r][i].z, a[r], c[r]), gg.z, bb.z);
                v[r][i].w = fmaf(fmaf(v[r][i].w, a[r], c[r]), gg.w, bb.w);
            }
        }

        // Roll the prefetch registers forward to pass p+1 (in flight during
        // the rest of this normalize + next stats/reduction).
        if (p < 2) {
            #pragma unroll
            for (int i = 0; i < 2; i++) {
                pgg[i] = __ldg(gtab[p + 1] + lane + 32 * i);
                pbb[i] = __ldg(btab[p + 1] + lane + 32 * i);
            }
        }

        // Normalize i=2,3 with direct loads (L1-hot tables).
        #pragma unroll
        for (int i = 2; i < 4; i++) {
            const float4 gg = __ldg(gvp + lane + 32 * i);
            const float4 bb = __ldg(bvp + lane + 32 * i);
            #pragma unroll
            for (int r = 0; r < ROWS; r++) {
                v[r][i].x = fmaf(fmaf(v[r][i].x, a[r], c[r]), gg.x, bb.x);
                v[r][i].y = fmaf(fmaf(v[r][i].y, a[r], c[r]), gg.y, bb.y);
                v[r][i].z = fmaf(fmaf(v[r][i].z, a[r], c[r]), gg.z, bb.z);
                v[r][i].w = fmaf(fmaf(v[r][i].w, a[r], c[r]), gg.w, bb.w);
            }
        }
    }

    float4* __restrict__ orow = reinterpret_cast<float4*>(out + elem0);
    #pragma unroll
    for (int r = 0; r < ROWS; r++)
        #pragma unroll
        for (int i = 0; i < 4; i++)
            orow[r * (D_DIM / 4) + lane + 32 * i] = v[r][i];
}

extern "C" void kernel_launch(void* const* d_in, const int* in_sizes, int n_in,
                              void* d_out, int out_size)
{
    const float* x  = (const float*)d_in[0];
    const int* pid  = (const int*)d_in[1];
    const int* cid  = (const int*)d_in[2];
    const int* tid  = (const int*)d_in[3];
    const float* pg = (const float*)d_in[4];
    const float* pb = (const float*)d_in[5];
    const float* cg = (const float*)d_in[6];
    const float* cb = (const float*)d_in[7];
    const float* tg = (const float*)d_in[8];
    const float* tb = (const float*)d_in[9];
    // d_in[10] = W, d_in[11] = b : unused (gated blend is the identity)
    float* out = (float*)d_out;

    dim3 grid(B_DIM * SPLIT);
    dim3 block(THREADS);
    bionorm_kernel<<<grid, block>>>(x, pid, cid, tid,
                                    pg, pb, cg, cb, tg, tb, out);
}